// round 1
// baseline (speedup 1.0000x reference)
#include <cuda_runtime.h>

#define IN_DIM   1024
#define OUT_DIM  512
#define BATCH    1024

#define BM 64
#define BN 64
#define BK 16

// scratch for per-output constant c[o] = sum_i (u*w)^2  (no allocs allowed)
__device__ float g_c[OUT_DIM];

// ---------------------------------------------------------------------------
// Kernel 1: c[o] = sum_i (u[o,i]*w[o,i])^2   — 512 blocks x 256 threads
// ---------------------------------------------------------------------------
__global__ __launch_bounds__(256) void rbf_c_kernel(const float* __restrict__ w,
                                                    const float* __restrict__ u) {
    int o = blockIdx.x;
    int t = threadIdx.x;
    const float* wo = w + (size_t)o * IN_DIM;
    const float* uo = u + (size_t)o * IN_DIM;
    float s = 0.f;
    #pragma unroll
    for (int i = t; i < IN_DIM; i += 256) {
        float uw = uo[i] * wo[i];
        s = fmaf(uw, uw, s);
    }
    __shared__ float red[256];
    red[t] = s;
    __syncthreads();
    for (int k = 128; k >= 32; k >>= 1) {
        if (t < k) red[t] += red[t + k];
        __syncthreads();
    }
    if (t < 32) {
        float v = red[t];
        #pragma unroll
        for (int off = 16; off > 0; off >>= 1)
            v += __shfl_down_sync(0xffffffffu, v, off);
        if (t == 0) g_c[o] = v;
    }
}

// ---------------------------------------------------------------------------
// Kernel 2: dual-GEMM  z[b,o] = sum_k A[o,k]*x2[b,k] + Bm[o,k]*x[b,k] + c[o]
//           out[b,o]  = ao + exp(-z) * (1 - 2*ao)
// Tile: 64(b) x 64(o) x 16(k), 256 threads, 4x4 microtile per thread.
// ---------------------------------------------------------------------------
__global__ __launch_bounds__(256) void rbf_main_kernel(
    const float* __restrict__ x, const float* __restrict__ w,
    const float* __restrict__ u, const float* __restrict__ andor,
    float* __restrict__ out)
{
    // +2 padding on the inner dim: breaks the kk-major STS bank conflict
    // (stride 66 float2 = 528B -> bank rotates by 4 per kk) while keeping
    // even-index float2 elements 16B-aligned for LDS.128.
    __shared__ float2 Qs[BK][BM + 2];   // (x, x^2)  per (k, b)
    __shared__ float2 Ps[BK][BN + 2];   // (A, Bm)   per (k, o)

    const int bm0 = blockIdx.y * BM;    // batch tile origin
    const int bn0 = blockIdx.x * BN;    // out tile origin
    const int tid = threadIdx.x;
    const int tx  = tid & 15;           // b microtile index   (16)
    const int ty  = tid >> 4;           // o microtile index   (16)

    float acc[4][4] = {};

    for (int k0 = 0; k0 < IN_DIM; k0 += BK) {
        // ---- fill Q tile: 64 b-rows x 16 k (1024 elems / 256 thr = 4 each)
        #pragma unroll
        for (int j = 0; j < 4; j++) {
            int idx = tid + j * 256;
            int kk = idx & 15;
            int bl = idx >> 4;
            float xv = x[(size_t)(bm0 + bl) * IN_DIM + k0 + kk];
            Qs[kk][bl] = make_float2(xv, xv * xv);
        }
        // ---- fill P tile: 64 o-rows x 16 k, A/Bm computed on the fly
        #pragma unroll
        for (int j = 0; j < 4; j++) {
            int idx = tid + j * 256;
            int kk = idx & 15;
            int ol = idx >> 4;
            size_t g = (size_t)(bn0 + ol) * IN_DIM + k0 + kk;
            float uv = u[g];
            float wv = w[g];
            float A  = uv * uv;
            Ps[kk][ol] = make_float2(A, -2.f * A * wv);
        }
        __syncthreads();

        #pragma unroll
        for (int kk = 0; kk < BK; kk++) {
            float2 qf[4], pf[4];
            #pragma unroll
            for (int i = 0; i < 4; i++) qf[i] = Qs[kk][tx * 4 + i];
            #pragma unroll
            for (int j = 0; j < 4; j++) pf[j] = Ps[kk][ty * 4 + j];
            #pragma unroll
            for (int i = 0; i < 4; i++)
                #pragma unroll
                for (int j = 0; j < 4; j++)
                    // acc += A * x^2 + Bm * x
                    acc[i][j] = fmaf(pf[j].x, qf[i].y,
                                fmaf(pf[j].y, qf[i].x, acc[i][j]));
        }
        __syncthreads();
    }

    // ---- epilogue: z -> exp(-z) -> andor mix; float4 stores (4 consecutive o)
    const int obase = bn0 + ty * 4;
    float cvals[4], mixm[4], mixa[4];
    #pragma unroll
    for (int j = 0; j < 4; j++) {
        cvals[j] = g_c[obase + j];
        float ao = andor[obase + j];
        mixa[j] = ao;
        mixm[j] = 1.f - 2.f * ao;
    }
    #pragma unroll
    for (int i = 0; i < 4; i++) {
        int b = bm0 + tx * 4 + i;
        float4 res;
        float* rp = &res.x;
        #pragma unroll
        for (int j = 0; j < 4; j++) {
            float z = acc[i][j] + cvals[j];
            float y = __expf(-z);
            rp[j] = fmaf(y, mixm[j], mixa[j]);
        }
        *reinterpret_cast<float4*>(&out[(size_t)b * OUT_DIM + obase]) = res;
    }
}

// ---------------------------------------------------------------------------
extern "C" void kernel_launch(void* const* d_in, const int* in_sizes, int n_in,
                              void* d_out, int out_size) {
    const float* x     = (const float*)d_in[0];   // [1024, 1024]
    const float* w     = (const float*)d_in[1];   // [512, 1024]
    const float* u     = (const float*)d_in[2];   // [512, 1024]
    const float* andor = (const float*)d_in[3];   // [1, 512]
    float* out = (float*)d_out;                   // [1024, 512]

    rbf_c_kernel<<<OUT_DIM, 256>>>(w, u);

    dim3 grid(OUT_DIM / BN, BATCH / BM);          // (8, 16) = 128 blocks
    rbf_main_kernel<<<grid, 256>>>(x, w, u, andor, out);
}

// round 3
// speedup vs baseline: 7.7678x; 7.7678x over previous
#include <cuda_runtime.h>
#include <cuda_bf16.h>
#include <cstdint>

#define IN_DIM   1024
#define OUT_DIM  512
#define BATCH    1024
#define K2       2048           // interleaved K dimension (2 terms per input)
#define BM       64             // batch rows per CTA
#define BN       64             // out cols per CTA
#define BK       64             // bf16 k per smem stage
#define NITER    (K2 / BK)      // 32
#define ROW_B    144            // smem row stride bytes (128 data + 16 pad)
#define TILE_B   (64 * ROW_B)   // 9216 per operand tile
#define STAGE_B  (2 * TILE_B)   // 18432 (A tile + B tile)

// ---------------- static scratch (no allocs allowed) ----------------
__device__ float          g_c[OUT_DIM];                    // exact fp32 c[o]
__device__ __nv_bfloat16  g_H[(size_t)BATCH  * K2];        // (x^2, x) interleaved
__device__ __nv_bfloat16  g_G[(size_t)OUT_DIM * K2];       // (u^2, -2u^2 w) interleaved

// ---------------- PTX helpers (baseline PTX only: sm_80-class ops) ----------
__device__ __forceinline__ uint32_t smem_u32(const void* p) {
    uint32_t a;
    asm("{ .reg .u64 t; cvta.to.shared.u64 t, %1; cvt.u32.u64 %0, t; }" : "=r"(a) : "l"(p));
    return a;
}
__device__ __forceinline__ void cp_async16(uint32_t dst, const void* src) {
    asm volatile("cp.async.cg.shared.global [%0], [%1], 16;" :: "r"(dst), "l"(src) : "memory");
}
#define CP_COMMIT()  asm volatile("cp.async.commit_group;" ::: "memory")
#define CP_WAIT(n)   asm volatile("cp.async.wait_group %0;" :: "n"(n) : "memory")

__device__ __forceinline__ void ldsm_x4(uint32_t& r0, uint32_t& r1, uint32_t& r2, uint32_t& r3,
                                        uint32_t addr) {
    asm volatile("ldmatrix.sync.aligned.m8n8.x4.shared.b16 {%0,%1,%2,%3}, [%4];"
                 : "=r"(r0), "=r"(r1), "=r"(r2), "=r"(r3) : "r"(addr));
}
__device__ __forceinline__ void mma16816(float* c, const uint32_t* a, const uint32_t* b) {
    asm volatile(
        "mma.sync.aligned.m16n8k16.row.col.f32.bf16.bf16.f32 "
        "{%0,%1,%2,%3}, {%4,%5,%6,%7}, {%8,%9}, {%0,%1,%2,%3};"
        : "+f"(c[0]), "+f"(c[1]), "+f"(c[2]), "+f"(c[3])
        : "r"(a[0]), "r"(a[1]), "r"(a[2]), "r"(a[3]), "r"(b[0]), "r"(b[1]));
}

// ---------------------------------------------------------------------------
// Prep: H[b, 2i] = bf16(x^2), H[b, 2i+1] = bf16(x)
// ---------------------------------------------------------------------------
__global__ __launch_bounds__(256) void prep_x_kernel(const float* __restrict__ x) {
    int idx = blockIdx.x * 256 + threadIdx.x;          // each handles 4 floats
    float4 v = reinterpret_cast<const float4*>(x)[idx];
    __nv_bfloat162 o0 = __nv_bfloat162(__float2bfloat16_rn(v.x * v.x), __float2bfloat16_rn(v.x));
    __nv_bfloat162 o1 = __nv_bfloat162(__float2bfloat16_rn(v.y * v.y), __float2bfloat16_rn(v.y));
    __nv_bfloat162 o2 = __nv_bfloat162(__float2bfloat16_rn(v.z * v.z), __float2bfloat16_rn(v.z));
    __nv_bfloat162 o3 = __nv_bfloat162(__float2bfloat16_rn(v.w * v.w), __float2bfloat16_rn(v.w));
    float4 pack;
    pack.x = __uint_as_float(*(uint32_t*)&o0);
    pack.y = __uint_as_float(*(uint32_t*)&o1);
    pack.z = __uint_as_float(*(uint32_t*)&o2);
    pack.w = __uint_as_float(*(uint32_t*)&o3);
    reinterpret_cast<float4*>(g_H)[idx] = pack;
}

// ---------------------------------------------------------------------------
// Prep: G[o, 2i] = bf16(u^2), G[o, 2i+1] = bf16(-2 u^2 w); also partial for c
// ---------------------------------------------------------------------------
__global__ __launch_bounds__(256) void prep_g_kernel(const float* __restrict__ w,
                                                     const float* __restrict__ u) {
    int idx = blockIdx.x * 256 + threadIdx.x;
    float4 uv = reinterpret_cast<const float4*>(u)[idx];
    float4 wv = reinterpret_cast<const float4*>(w)[idx];
    float a0 = uv.x * uv.x, a1 = uv.y * uv.y, a2 = uv.z * uv.z, a3 = uv.w * uv.w;
    __nv_bfloat162 o0 = __nv_bfloat162(__float2bfloat16_rn(a0), __float2bfloat16_rn(-2.f * a0 * wv.x));
    __nv_bfloat162 o1 = __nv_bfloat162(__float2bfloat16_rn(a1), __float2bfloat16_rn(-2.f * a1 * wv.y));
    __nv_bfloat162 o2 = __nv_bfloat162(__float2bfloat16_rn(a2), __float2bfloat16_rn(-2.f * a2 * wv.z));
    __nv_bfloat162 o3 = __nv_bfloat162(__float2bfloat16_rn(a3), __float2bfloat16_rn(-2.f * a3 * wv.w));
    float4 pack;
    pack.x = __uint_as_float(*(uint32_t*)&o0);
    pack.y = __uint_as_float(*(uint32_t*)&o1);
    pack.z = __uint_as_float(*(uint32_t*)&o2);
    pack.w = __uint_as_float(*(uint32_t*)&o3);
    reinterpret_cast<float4*>(g_G)[idx] = pack;
}

// ---------------------------------------------------------------------------
// c[o] = sum_i (u[o,i]*w[o,i])^2  (exact fp32)
// ---------------------------------------------------------------------------
__global__ __launch_bounds__(256) void rbf_c_kernel(const float* __restrict__ w,
                                                    const float* __restrict__ u) {
    int o = blockIdx.x;
    int t = threadIdx.x;
    const float* wo = w + (size_t)o * IN_DIM;
    const float* uo = u + (size_t)o * IN_DIM;
    float s = 0.f;
    #pragma unroll
    for (int i = t; i < IN_DIM; i += 256) {
        float uw = uo[i] * wo[i];
        s = fmaf(uw, uw, s);
    }
    __shared__ float red[256];
    red[t] = s;
    __syncthreads();
    for (int k = 128; k >= 32; k >>= 1) {
        if (t < k) red[t] += red[t + k];
        __syncthreads();
    }
    if (t < 32) {
        float v = red[t];
        #pragma unroll
        for (int off = 16; off > 0; off >>= 1)
            v += __shfl_down_sync(0xffffffffu, v, off);
        if (t == 0) g_c[o] = v;
    }
}

// ---------------------------------------------------------------------------
// Main: bf16 mma.sync dual-GEMM + fused epilogue
// grid = (OUT/64, BATCH/64) = (8, 16) = 128 CTAs, 128 threads (4 warps)
// warp layout 2x2: warp tile 32(m) x 32(n); k per stage = 64 (4 x k16)
// ---------------------------------------------------------------------------
__global__ __launch_bounds__(128) void rbf_hmma_kernel(const float* __restrict__ andor,
                                                       float* __restrict__ out) {
    __shared__ __align__(16) char smem[2 * STAGE_B];   // 36864 B, double-buffered
    const uint32_t smem_base = smem_u32(smem);

    const int tid  = threadIdx.x;
    const int wid  = tid >> 5;
    const int lane = tid & 31;
    const int bn0  = blockIdx.x * BN;     // out-tile origin
    const int bm0  = blockIdx.y * BM;     // batch-tile origin
    const int wm   = (wid & 1) * 32;      // warp m offset in tile
    const int wn   = (wid >> 1) * 32;     // warp n offset in tile

    // ---- async load of one stage (A: H rows, B: G rows), 8 x 16B per thread
    auto load_stage = [&](int slot, int k0) {
        #pragma unroll
        for (int it = 0; it < 8; it++) {
            int idx  = tid + it * 128;        // 0..1023
            int half = idx >> 9;              // 0 = A(H), 1 = B(G)
            int r    = (idx >> 3) & 63;
            int ch   = idx & 7;               // 16B chunk (8 bf16)
            const __nv_bfloat16* src = half
                ? g_G + (size_t)(bn0 + r) * K2 + k0 + ch * 8
                : g_H + (size_t)(bm0 + r) * K2 + k0 + ch * 8;
            uint32_t dst = smem_base + slot * STAGE_B + half * TILE_B + r * ROW_B + ch * 16;
            cp_async16(dst, src);
        }
        CP_COMMIT();
    };

    float acc[2][4][4] = {};   // [m atom][n atom][frag]

    load_stage(0, 0);
    load_stage(1, BK);

    // ldmatrix lane-address components (within a tile)
    const int a_row = (lane & 7) + ((lane >> 3) & 1) * 8;   // m row within 16
    const int a_kb  = (lane >> 4) * 16;                     // k byte within 32
    const int b_row = (lane & 7) + ((lane >> 4) << 3);      // n row within 16
    const int b_kb  = ((lane >> 3) & 1) * 16;

    for (int s = 0; s < NITER; s++) {
        CP_WAIT(1);            // stage s resident
        __syncthreads();

        const uint32_t aBase = smem_base + (s & 1) * STAGE_B;
        const uint32_t bBase = aBase + TILE_B;

        #pragma unroll
        for (int kk = 0; kk < 4; kk++) {        // 4 x k16 per stage
            uint32_t a[2][4], b[2][4];
            #pragma unroll
            for (int im = 0; im < 2; im++)
                ldsm_x4(a[im][0], a[im][1], a[im][2], a[im][3],
                        aBase + (wm + im * 16 + a_row) * ROW_B + kk * 32 + a_kb);
            #pragma unroll
            for (int g = 0; g < 2; g++)
                ldsm_x4(b[g][0], b[g][1], b[g][2], b[g][3],
                        bBase + (wn + g * 16 + b_row) * ROW_B + kk * 32 + b_kb);
            #pragma unroll
            for (int im = 0; im < 2; im++)
                #pragma unroll
                for (int in = 0; in < 4; in++)
                    mma16816(acc[im][in], a[im], &b[in >> 1][(in & 1) * 2]);
        }
        __syncthreads();
        if (s + 2 < NITER) load_stage(s & 1, (s + 2) * BK);
    }

    // ---- epilogue: z = acc + c[o]; y = exp(-z); out = a + y*(1-2a)
    #pragma unroll
    for (int im = 0; im < 2; im++) {
        const int row0 = bm0 + wm + im * 16 + (lane >> 2);
        #pragma unroll
        for (int in = 0; in < 4; in++) {
            const int col = bn0 + wn + in * 8 + (lane & 3) * 2;
            const float c0 = g_c[col],     c1 = g_c[col + 1];
            const float a0 = andor[col],   a1 = andor[col + 1];
            const float m0 = 1.f - 2.f * a0, m1 = 1.f - 2.f * a1;
            float2 r;
            r.x = fmaf(__expf(-(acc[im][in][0] + c0)), m0, a0);
            r.y = fmaf(__expf(-(acc[im][in][1] + c1)), m1, a1);
            *reinterpret_cast<float2*>(&out[(size_t)row0 * OUT_DIM + col]) = r;
            r.x = fmaf(__expf(-(acc[im][in][2] + c0)), m0, a0);
            r.y = fmaf(__expf(-(acc[im][in][3] + c1)), m1, a1);
            *reinterpret_cast<float2*>(&out[(size_t)(row0 + 8) * OUT_DIM + col]) = r;
        }
    }
}

// ---------------------------------------------------------------------------
extern "C" void kernel_launch(void* const* d_in, const int* in_sizes, int n_in,
                              void* d_out, int out_size) {
    const float* x     = (const float*)d_in[0];   // [1024, 1024]
    const float* w     = (const float*)d_in[1];   // [512, 1024]
    const float* u     = (const float*)d_in[2];   // [512, 1024]
    const float* andor = (const float*)d_in[3];   // [1, 512]
    float* out = (float*)d_out;                   // [1024, 512]

    prep_x_kernel<<<BATCH * IN_DIM / 4 / 256, 256>>>(x);
    prep_g_kernel<<<OUT_DIM * IN_DIM / 4 / 256, 256>>>(w, u);
    rbf_c_kernel<<<OUT_DIM, 256>>>(w, u);

    dim3 grid(OUT_DIM / BN, BATCH / BM);          // (8, 16) = 128 CTAs
    rbf_hmma_kernel<<<grid, 128>>>(andor, out);
}

// round 4
// speedup vs baseline: 9.1435x; 1.1771x over previous
#include <cuda_runtime.h>
#include <cuda_bf16.h>
#include <cstdint>

#define IN_DIM   1024
#define OUT_DIM  512
#define BATCH    1024
#define K2       2048           // interleaved K dimension (2 terms per input)
#define BM       64             // batch rows per CTA
#define BN       64             // out cols per CTA
#define BK       64             // bf16 k per smem stage (= 128B per row)
#define NITER    (K2 / BK)      // 32
#define ROW_B    128            // smem row stride (XOR swizzle, no padding)
#define TILE_B   (64 * ROW_B)   // 8192 per operand tile
#define STAGE_B  (2 * TILE_B)   // 16384 (A tile + B tile)
#define NSTAGE   3              // 3 * 16384 = 49152 = 48KB static smem

// ---------------- static scratch (no allocs allowed) ----------------
__device__ float          g_c[OUT_DIM];                    // exact fp32 c[o]
__device__ __nv_bfloat16  g_H[(size_t)BATCH  * K2];        // (x^2, x) interleaved
__device__ __nv_bfloat16  g_G[(size_t)OUT_DIM * K2];       // (u^2, -2u^2 w) interleaved

// ---------------- PTX helpers (baseline PTX only: sm_80-class ops) ----------
__device__ __forceinline__ uint32_t smem_u32(const void* p) {
    uint32_t a;
    asm("{ .reg .u64 t; cvta.to.shared.u64 t, %1; cvt.u32.u64 %0, t; }" : "=r"(a) : "l"(p));
    return a;
}
__device__ __forceinline__ void cp_async16(uint32_t dst, const void* src) {
    asm volatile("cp.async.cg.shared.global [%0], [%1], 16;" :: "r"(dst), "l"(src) : "memory");
}
#define CP_COMMIT()  asm volatile("cp.async.commit_group;" ::: "memory")
#define CP_WAIT(n)   asm volatile("cp.async.wait_group %0;" :: "n"(n) : "memory")

__device__ __forceinline__ void ldsm_x4(uint32_t& r0, uint32_t& r1, uint32_t& r2, uint32_t& r3,
                                        uint32_t addr) {
    asm volatile("ldmatrix.sync.aligned.m8n8.x4.shared.b16 {%0,%1,%2,%3}, [%4];"
                 : "=r"(r0), "=r"(r1), "=r"(r2), "=r"(r3) : "r"(addr));
}
__device__ __forceinline__ void mma16816(float* c, const uint32_t* a, const uint32_t* b) {
    asm volatile(
        "mma.sync.aligned.m16n8k16.row.col.f32.bf16.bf16.f32 "
        "{%0,%1,%2,%3}, {%4,%5,%6,%7}, {%8,%9}, {%0,%1,%2,%3};"
        : "+f"(c[0]), "+f"(c[1]), "+f"(c[2]), "+f"(c[3])
        : "r"(a[0]), "r"(a[1]), "r"(a[2]), "r"(a[3]), "r"(b[0]), "r"(b[1]));
}

// ---------------------------------------------------------------------------
// Prep: H[b, 2i] = bf16(x^2), H[b, 2i+1] = bf16(x)
// ---------------------------------------------------------------------------
__global__ __launch_bounds__(256) void prep_x_kernel(const float* __restrict__ x) {
    int idx = blockIdx.x * 256 + threadIdx.x;          // each handles 4 floats
    float4 v = reinterpret_cast<const float4*>(x)[idx];
    __nv_bfloat162 o0 = __nv_bfloat162(__float2bfloat16_rn(v.x * v.x), __float2bfloat16_rn(v.x));
    __nv_bfloat162 o1 = __nv_bfloat162(__float2bfloat16_rn(v.y * v.y), __float2bfloat16_rn(v.y));
    __nv_bfloat162 o2 = __nv_bfloat162(__float2bfloat16_rn(v.z * v.z), __float2bfloat16_rn(v.z));
    __nv_bfloat162 o3 = __nv_bfloat162(__float2bfloat16_rn(v.w * v.w), __float2bfloat16_rn(v.w));
    float4 pack;
    pack.x = __uint_as_float(*(uint32_t*)&o0);
    pack.y = __uint_as_float(*(uint32_t*)&o1);
    pack.z = __uint_as_float(*(uint32_t*)&o2);
    pack.w = __uint_as_float(*(uint32_t*)&o3);
    reinterpret_cast<float4*>(g_H)[idx] = pack;
}

// ---------------------------------------------------------------------------
// Fused prep: G[o, 2i] = bf16(u^2), G[o, 2i+1] = bf16(-2 u^2 w),
//             c[o] = sum_i (u w)^2  (exact fp32).  One block per output o.
// ---------------------------------------------------------------------------
__global__ __launch_bounds__(256) void prep_g_c_kernel(const float* __restrict__ w,
                                                       const float* __restrict__ u) {
    const int o = blockIdx.x;
    const int t = threadIdx.x;
    float4 uv = reinterpret_cast<const float4*>(u + (size_t)o * IN_DIM)[t];
    float4 wv = reinterpret_cast<const float4*>(w + (size_t)o * IN_DIM)[t];

    float a0 = uv.x * uv.x, a1 = uv.y * uv.y, a2 = uv.z * uv.z, a3 = uv.w * uv.w;
    __nv_bfloat162 o0 = __nv_bfloat162(__float2bfloat16_rn(a0), __float2bfloat16_rn(-2.f * a0 * wv.x));
    __nv_bfloat162 o1 = __nv_bfloat162(__float2bfloat16_rn(a1), __float2bfloat16_rn(-2.f * a1 * wv.y));
    __nv_bfloat162 o2 = __nv_bfloat162(__float2bfloat16_rn(a2), __float2bfloat16_rn(-2.f * a2 * wv.z));
    __nv_bfloat162 o3 = __nv_bfloat162(__float2bfloat16_rn(a3), __float2bfloat16_rn(-2.f * a3 * wv.w));
    float4 pack;
    pack.x = __uint_as_float(*(uint32_t*)&o0);
    pack.y = __uint_as_float(*(uint32_t*)&o1);
    pack.z = __uint_as_float(*(uint32_t*)&o2);
    pack.w = __uint_as_float(*(uint32_t*)&o3);
    reinterpret_cast<float4*>(g_G + (size_t)o * K2)[t] = pack;

    // c[o] reduction
    float p0 = uv.x * wv.x, p1 = uv.y * wv.y, p2 = uv.z * wv.z, p3 = uv.w * wv.w;
    float s = fmaf(p0, p0, fmaf(p1, p1, fmaf(p2, p2, p3 * p3)));
    __shared__ float red[256];
    red[t] = s;
    __syncthreads();
    for (int k = 128; k >= 32; k >>= 1) {
        if (t < k) red[t] += red[t + k];
        __syncthreads();
    }
    if (t < 32) {
        float v = red[t];
        #pragma unroll
        for (int off = 16; off > 0; off >>= 1)
            v += __shfl_down_sync(0xffffffffu, v, off);
        if (t == 0) g_c[o] = v;
    }
}

// ---------------------------------------------------------------------------
// Main: bf16 mma.sync dual-GEMM + fused epilogue
// grid = (OUT/64, BATCH/64) = (8, 16) = 128 CTAs, 256 threads (8 warps)
// warp grid 2(m) x 4(n): warp tile 32 x 16; 3-stage cp.async pipeline.
// smem: XOR-swizzled 128B rows (chunk ^= row&7) -> conflict-free STS + LDSM.
// ---------------------------------------------------------------------------
__global__ __launch_bounds__(256) void rbf_hmma_kernel(const float* __restrict__ andor,
                                                       float* __restrict__ out) {
    __shared__ __align__(16) char smem[NSTAGE * STAGE_B];   // 49152 B
    const uint32_t smem_base = smem_u32(smem);

    const int tid  = threadIdx.x;
    const int wid  = tid >> 5;
    const int lane = tid & 31;
    const int bn0  = blockIdx.x * BN;     // out-tile origin
    const int bm0  = blockIdx.y * BM;     // batch-tile origin
    const int wm   = (wid & 1) * 32;      // warp m offset (2 warps)
    const int wn   = (wid >> 1) * 16;     // warp n offset (4 warps)

    // ---- async load of one stage (A: H rows, B: G rows), 4 x 16B per thread
    auto load_stage = [&](int slot, int k0) {
        #pragma unroll
        for (int it = 0; it < 4; it++) {
            int idx  = tid + it * 256;        // 0..1023
            int half = idx >> 9;              // 0 = A(H), 1 = B(G)
            int r    = (idx >> 3) & 63;
            int ch   = idx & 7;               // logical 16B chunk (8 bf16)
            const __nv_bfloat16* src = half
                ? g_G + (size_t)(bn0 + r) * K2 + k0 + ch * 8
                : g_H + (size_t)(bm0 + r) * K2 + k0 + ch * 8;
            uint32_t dst = smem_base + slot * STAGE_B + half * TILE_B
                         + r * ROW_B + ((ch ^ (r & 7)) << 4);
            cp_async16(dst, src);
        }
        CP_COMMIT();
    };

    float acc[2][2][4] = {};   // [m16 atom][n8 atom][frag]

    load_stage(0, 0);
    load_stage(1, BK);
    load_stage(2, 2 * BK);

    // ldmatrix lane-address components
    const int a_row = (lane & 7) + ((lane >> 3) & 1) * 8;   // m row within 16
    const int a_ch  = (lane >> 4);                          // logical chunk LSB
    const int b_row = (lane & 7) + ((lane >> 4) << 3);      // n row within 16
    const int b_ch  = ((lane >> 3) & 1);

    for (int s = 0; s < NITER; s++) {
        CP_WAIT(2);            // stage s resident (3 groups outstanding max)
        __syncthreads();       // all warps' loads for stage s visible

        const uint32_t aBase = smem_base + (s % NSTAGE) * STAGE_B;
        const uint32_t bBase = aBase + TILE_B;

        #pragma unroll
        for (int kk = 0; kk < 4; kk++) {        // 4 x k16 per stage
            uint32_t a[2][4], b[4];
            #pragma unroll
            for (int im = 0; im < 2; im++) {
                int row = wm + im * 16 + a_row;
                ldsm_x4(a[im][0], a[im][1], a[im][2], a[im][3],
                        aBase + row * ROW_B + (((kk * 2 + a_ch) ^ (row & 7)) << 4));
            }
            {
                int row = wn + b_row;
                ldsm_x4(b[0], b[1], b[2], b[3],
                        bBase + row * ROW_B + (((kk * 2 + b_ch) ^ (row & 7)) << 4));
            }
            #pragma unroll
            for (int im = 0; im < 2; im++)
                #pragma unroll
                for (int in = 0; in < 2; in++)
                    mma16816(acc[im][in], a[im], &b[in * 2]);
        }
        __syncthreads();       // all warps done reading slot before refill
        if (s + 3 < NITER) load_stage(s % NSTAGE, (s + 3) * BK);
        else CP_COMMIT();      // keep group count invariant for CP_WAIT(2)
    }

    // ---- epilogue: z = acc + c[o]; y = exp(-z); out = a + y*(1-2a)
    #pragma unroll
    for (int im = 0; im < 2; im++) {
        const int row0 = bm0 + wm + im * 16 + (lane >> 2);
        #pragma unroll
        for (int in = 0; in < 2; in++) {
            const int col = bn0 + wn + in * 8 + (lane & 3) * 2;
            const float c0 = g_c[col],     c1 = g_c[col + 1];
            const float a0 = andor[col],   a1 = andor[col + 1];
            const float m0 = 1.f - 2.f * a0, m1 = 1.f - 2.f * a1;
            float2 r;
            r.x = fmaf(__expf(-(acc[im][in][0] + c0)), m0, a0);
            r.y = fmaf(__expf(-(acc[im][in][1] + c1)), m1, a1);
            *reinterpret_cast<float2*>(&out[(size_t)row0 * OUT_DIM + col]) = r;
            r.x = fmaf(__expf(-(acc[im][in][2] + c0)), m0, a0);
            r.y = fmaf(__expf(-(acc[im][in][3] + c1)), m1, a1);
            *reinterpret_cast<float2*>(&out[(size_t)(row0 + 8) * OUT_DIM + col]) = r;
        }
    }
}

// ---------------------------------------------------------------------------
extern "C" void kernel_launch(void* const* d_in, const int* in_sizes, int n_in,
                              void* d_out, int out_size) {
    const float* x     = (const float*)d_in[0];   // [1024, 1024]
    const float* w     = (const float*)d_in[1];   // [512, 1024]
    const float* u     = (const float*)d_in[2];   // [512, 1024]
    const float* andor = (const float*)d_in[3];   // [1, 512]
    float* out = (float*)d_out;                   // [1024, 512]

    prep_x_kernel<<<BATCH * IN_DIM / 4 / 256, 256>>>(x);
    prep_g_c_kernel<<<OUT_DIM, 256>>>(w, u);

    dim3 grid(OUT_DIM / BN, BATCH / BM);          // (8, 16) = 128 CTAs
    rbf_hmma_kernel<<<grid, 256>>>(andor, out);
}

// round 5
// speedup vs baseline: 10.1166x; 1.1064x over previous
#include <cuda_runtime.h>
#include <cuda_bf16.h>
#include <cstdint>

#define IN_DIM   1024
#define OUT_DIM  512
#define BATCH    1024
#define K2       2048           // interleaved K dimension (2 terms per input)
#define BM       64             // batch rows per CTA
#define BN       64             // out cols per CTA
#define BK       64             // bf16 k per smem stage (= 128B per row)
#define NITER    (K2 / BK)      // 32
#define ROW_B    128            // smem row stride (XOR swizzle, no padding)
#define TILE_B   (64 * ROW_B)   // 8192 per operand tile
#define STAGE_B  (2 * TILE_B)   // 16384 (A tile + B tile)
#define NSTAGE   4              // 4 * 16384 = 65536 B dynamic smem
#define SMEM_TOT (NSTAGE * STAGE_B)

// ---------------- static scratch (no allocs allowed) ----------------
__device__ float          g_c[OUT_DIM];                    // exact fp32 c[o]
__device__ __nv_bfloat16  g_H[(size_t)BATCH  * K2];        // (x^2, x) interleaved
__device__ __nv_bfloat16  g_G[(size_t)OUT_DIM * K2];       // (u^2, -2u^2 w) interleaved

// ---------------- PTX helpers (baseline PTX only: sm_80-class ops) ----------
__device__ __forceinline__ uint32_t smem_u32(const void* p) {
    uint32_t a;
    asm("{ .reg .u64 t; cvta.to.shared.u64 t, %1; cvt.u32.u64 %0, t; }" : "=r"(a) : "l"(p));
    return a;
}
__device__ __forceinline__ void cp_async16(uint32_t dst, const void* src) {
    asm volatile("cp.async.cg.shared.global [%0], [%1], 16;" :: "r"(dst), "l"(src) : "memory");
}
#define CP_COMMIT()  asm volatile("cp.async.commit_group;" ::: "memory")
#define CP_WAIT(n)   asm volatile("cp.async.wait_group %0;" :: "n"(n) : "memory")

__device__ __forceinline__ void ldsm_x4(uint32_t& r0, uint32_t& r1, uint32_t& r2, uint32_t& r3,
                                        uint32_t addr) {
    asm volatile("ldmatrix.sync.aligned.m8n8.x4.shared.b16 {%0,%1,%2,%3}, [%4];"
                 : "=r"(r0), "=r"(r1), "=r"(r2), "=r"(r3) : "r"(addr));
}
__device__ __forceinline__ void mma16816(float* c, const uint32_t* a, const uint32_t* b) {
    asm volatile(
        "mma.sync.aligned.m16n8k16.row.col.f32.bf16.bf16.f32 "
        "{%0,%1,%2,%3}, {%4,%5,%6,%7}, {%8,%9}, {%0,%1,%2,%3};"
        : "+f"(c[0]), "+f"(c[1]), "+f"(c[2]), "+f"(c[3])
        : "r"(a[0]), "r"(a[1]), "r"(a[2]), "r"(a[3]), "r"(b[0]), "r"(b[1]));
}

__device__ __forceinline__ float pack_bf2(float hi_from_lo, float lo) {
    __nv_bfloat162 t = __nv_bfloat162(__float2bfloat16_rn(hi_from_lo), __float2bfloat16_rn(lo));
    return __uint_as_float(*(uint32_t*)&t);
}

// ---------------------------------------------------------------------------
// Fused prep (one launch):
//   blocks [0,256):   H[b, 2i]=bf16(x^2), H[b, 2i+1]=bf16(x)     MLP=4
//   blocks [256,768): G[o, 2i]=bf16(u^2), G[o, 2i+1]=bf16(-2u^2w)
//                     + exact fp32 c[o] = sum (u w)^2
// ---------------------------------------------------------------------------
__global__ __launch_bounds__(256) void prep_all_kernel(const float* __restrict__ x,
                                                       const float* __restrict__ w,
                                                       const float* __restrict__ u) {
    const int t = threadIdx.x;
    if (blockIdx.x < 256) {
        const int base = blockIdx.x * 1024;       // float4 index base (4 per thread)
        float4 v[4];
        #pragma unroll
        for (int j = 0; j < 4; j++)               // batch the 4 loads -> MLP=4
            v[j] = reinterpret_cast<const float4*>(x)[base + t + j * 256];
        #pragma unroll
        for (int j = 0; j < 4; j++) {
            float4 p;
            p.x = pack_bf2(v[j].x * v[j].x, v[j].x);
            p.y = pack_bf2(v[j].y * v[j].y, v[j].y);
            p.z = pack_bf2(v[j].z * v[j].z, v[j].z);
            p.w = pack_bf2(v[j].w * v[j].w, v[j].w);
            reinterpret_cast<float4*>(g_H)[base + t + j * 256] = p;
        }
    } else {
        const int o = blockIdx.x - 256;
        float4 uv = reinterpret_cast<const float4*>(u + (size_t)o * IN_DIM)[t];
        float4 wv = reinterpret_cast<const float4*>(w + (size_t)o * IN_DIM)[t];

        float a0 = uv.x * uv.x, a1 = uv.y * uv.y, a2 = uv.z * uv.z, a3 = uv.w * uv.w;
        float4 p;
        p.x = pack_bf2(a0, -2.f * a0 * wv.x);
        p.y = pack_bf2(a1, -2.f * a1 * wv.y);
        p.z = pack_bf2(a2, -2.f * a2 * wv.z);
        p.w = pack_bf2(a3, -2.f * a3 * wv.w);
        reinterpret_cast<float4*>(g_G + (size_t)o * K2)[t] = p;

        float p0 = uv.x * wv.x, p1 = uv.y * wv.y, p2 = uv.z * wv.z, p3 = uv.w * wv.w;
        float s = fmaf(p0, p0, fmaf(p1, p1, fmaf(p2, p2, p3 * p3)));
        __shared__ float red[256];
        red[t] = s;
        __syncthreads();
        for (int k = 128; k >= 32; k >>= 1) {
            if (t < k) red[t] += red[t + k];
            __syncthreads();
        }
        if (t < 32) {
            float v = red[t];
            #pragma unroll
            for (int off = 16; off > 0; off >>= 1)
                v += __shfl_down_sync(0xffffffffu, v, off);
            if (t == 0) g_c[o] = v;
        }
    }
}

// ---------------------------------------------------------------------------
// Main: bf16 mma.sync dual-GEMM + fused epilogue
// grid = (OUT/64, BATCH/64) = (8, 16) = 128 CTAs, 256 threads (8 warps)
// warp grid 2(m) x 4(n): warp tile 32 x 16.
// 4-stage cp.async pipeline, prefetch distance 3, ONE barrier per iter.
// smem: XOR-swizzled 128B rows (chunk ^= row&7) -> conflict-free STS + LDSM.
// ---------------------------------------------------------------------------
__global__ __launch_bounds__(256) void rbf_hmma_kernel(const float* __restrict__ andor,
                                                       float* __restrict__ out) {
    extern __shared__ __align__(16) char smem[];        // SMEM_TOT = 64KB dynamic
    const uint32_t smem_base = smem_u32(smem);

    const int tid  = threadIdx.x;
    const int wid  = tid >> 5;
    const int lane = tid & 31;
    const int bn0  = blockIdx.x * BN;     // out-tile origin
    const int bm0  = blockIdx.y * BM;     // batch-tile origin
    const int wm   = (wid & 1) * 32;      // warp m offset (2 warps)
    const int wn   = (wid >> 1) * 16;     // warp n offset (4 warps)

    // ---- async load of one stage (A: H rows, B: G rows), 4 x 16B per thread
    auto load_stage = [&](int slot, int k0) {
        #pragma unroll
        for (int it = 0; it < 4; it++) {
            int idx  = tid + it * 256;        // 0..1023
            int half = idx >> 9;              // 0 = A(H), 1 = B(G)
            int r    = (idx >> 3) & 63;
            int ch   = idx & 7;               // logical 16B chunk (8 bf16)
            const __nv_bfloat16* src = half
                ? g_G + (size_t)(bn0 + r) * K2 + k0 + ch * 8
                : g_H + (size_t)(bm0 + r) * K2 + k0 + ch * 8;
            uint32_t dst = smem_base + slot * STAGE_B + half * TILE_B
                         + r * ROW_B + ((ch ^ (r & 7)) << 4);
            cp_async16(dst, src);
        }
        CP_COMMIT();
    };

    float acc[2][2][4] = {};   // [m16 atom][n8 atom][frag]

    load_stage(0, 0);
    load_stage(1, BK);
    load_stage(2, 2 * BK);

    // ldmatrix lane-address components
    const int a_row = (lane & 7) + ((lane >> 3) & 1) * 8;   // m row within 16
    const int a_ch  = (lane >> 4);                          // logical chunk LSB
    const int b_row = (lane & 7) + ((lane >> 4) << 3);      // n row within 16
    const int b_ch  = ((lane >> 3) & 1);

    for (int s = 0; s < NITER; s++) {
        CP_WAIT(2);            // pending groups {s,s+1,s+2} -> group s resident
        __syncthreads();       // loads visible AND all warps done with iter s-1
                               // (slot (s+3)&3 == (s-1)&3 is now reusable)
        if (s + 3 < NITER) load_stage((s + 3) & 3, (s + 3) * BK);
        else CP_COMMIT();      // empty group keeps CP_WAIT(2) counting exact

        const uint32_t aBase = smem_base + (s & 3) * STAGE_B;
        const uint32_t bBase = aBase + TILE_B;

        #pragma unroll
        for (int kk = 0; kk < 4; kk++) {        // 4 x k16 per stage
            uint32_t a[2][4], b[4];
            #pragma unroll
            for (int im = 0; im < 2; im++) {
                int row = wm + im * 16 + a_row;
                ldsm_x4(a[im][0], a[im][1], a[im][2], a[im][3],
                        aBase + row * ROW_B + (((kk * 2 + a_ch) ^ (row & 7)) << 4));
            }
            {
                int row = wn + b_row;
                ldsm_x4(b[0], b[1], b[2], b[3],
                        bBase + row * ROW_B + (((kk * 2 + b_ch) ^ (row & 7)) << 4));
            }
            #pragma unroll
            for (int im = 0; im < 2; im++)
                #pragma unroll
                for (int in = 0; in < 2; in++)
                    mma16816(acc[im][in], a[im], &b[in * 2]);
        }
    }

    // ---- epilogue: z = acc + c[o]; y = exp(-z); out = a + y*(1-2a)
    #pragma unroll
    for (int im = 0; im < 2; im++) {
        const int row0 = bm0 + wm + im * 16 + (lane >> 2);
        #pragma unroll
        for (int in = 0; in < 2; in++) {
            const int col = bn0 + wn + in * 8 + (lane & 3) * 2;
            const float c0 = g_c[col],     c1 = g_c[col + 1];
            const float a0 = andor[col],   a1 = andor[col + 1];
            const float m0 = 1.f - 2.f * a0, m1 = 1.f - 2.f * a1;
            float2 r;
            r.x = fmaf(__expf(-(acc[im][in][0] + c0)), m0, a0);
            r.y = fmaf(__expf(-(acc[im][in][1] + c1)), m1, a1);
            *reinterpret_cast<float2*>(&out[(size_t)row0 * OUT_DIM + col]) = r;
            r.x = fmaf(__expf(-(acc[im][in][2] + c0)), m0, a0);
            r.y = fmaf(__expf(-(acc[im][in][3] + c1)), m1, a1);
            *reinterpret_cast<float2*>(&out[(size_t)(row0 + 8) * OUT_DIM + col]) = r;
        }
    }
}

// ---------------------------------------------------------------------------
extern "C" void kernel_launch(void* const* d_in, const int* in_sizes, int n_in,
                              void* d_out, int out_size) {
    const float* x     = (const float*)d_in[0];   // [1024, 1024]
    const float* w     = (const float*)d_in[1];   // [512, 1024]
    const float* u     = (const float*)d_in[2];   // [512, 1024]
    const float* andor = (const float*)d_in[3];   // [1, 512]
    float* out = (float*)d_out;                   // [1024, 512]

    // host-side attribute set (not a stream op; capture-safe, replay-free)
    cudaFuncSetAttribute(rbf_hmma_kernel,
                         cudaFuncAttributeMaxDynamicSharedMemorySize, SMEM_TOT);

    prep_all_kernel<<<256 + OUT_DIM, 256>>>(x, w, u);

    dim3 grid(OUT_DIM / BN, BATCH / BM);          // (8, 16) = 128 CTAs
    rbf_hmma_kernel<<<grid, 256, SMEM_TOT>>>(andor, out);
}